// round 1
// baseline (speedup 1.0000x reference)
#include <cuda_runtime.h>
#include <math.h>

typedef unsigned long long u64;

#define BATCH 16384
#define NF 10
#define LL 20
#define DD 16
#define FEAT 160
#define NE 8
#define SS 64
#define NG 3
#define TT 32
#define NCOLS (NE*SS)

// Scratch (device globals: no allocation allowed)
__device__ __align__(16) float g_xT[FEAT * BATCH];    // x transposed: [feat][b]
__device__ __align__(16) float g_expT[NCOLS * BATCH]; // experts transposed: [e*64+s][b]

__device__ __forceinline__ u64 pack2(float lo, float hi) {
    u64 d;
    asm("mov.b64 %0, {%1, %2};" : "=l"(d)
        : "r"(__float_as_uint(lo)), "r"(__float_as_uint(hi)));
    return d;
}
__device__ __forceinline__ void unpack2(u64 v, float &lo, float &hi) {
    unsigned a, b;
    asm("mov.b64 {%0, %1}, %2;" : "=r"(a), "=r"(b) : "l"(v));
    lo = __uint_as_float(a); hi = __uint_as_float(b);
}
__device__ __forceinline__ u64 ffma2(u64 a, u64 b, u64 c) {
    u64 d;
    asm("fma.rn.f32x2 %0, %1, %2, %3;" : "=l"(d) : "l"(a), "l"(b), "l"(c));
    return d;
}

// ---------------------------------------------------------------------------
// Kernel A: embedding gather + sum over L, write xT[feat][b]
// 4 lanes per (f,b) pair; each lane owns 4 of the 16 embedding dims (float4).
// ---------------------------------------------------------------------------
__global__ __launch_bounds__(256) void gather_kernel(const int* __restrict__ ids32,
                                                     const float4* __restrict__ emb) {
    __shared__ int s_is64;
    if (threadIdx.x == 0) {
        // ids values are < 2^20; if dtype is int64 the odd 32-bit words are 0.
        const unsigned* w = (const unsigned*)ids32;
        s_is64 = (w[1] == 0u && w[3] == 0u && w[5] == 0u && w[7] == 0u) ? 1 : 0;
    }
    __syncthreads();
    const int is64 = s_is64;

    int tid  = threadIdx.x;
    int p    = blockIdx.x * 64 + (tid >> 2);  // p = f*BATCH + b
    int lane = tid & 3;
    int f = p >> 14;
    int b = p & (BATCH - 1);
    long base = (long)p * LL;

    float4 acc = make_float4(0.f, 0.f, 0.f, 0.f);
    if (is64) {
        #pragma unroll
        for (int l = 0; l < LL; l++) {
            int id = ids32[2 * (base + l)];       // low word of int64
            float4 v = __ldg(&emb[(long)id * 4 + lane]);
            acc.x += v.x; acc.y += v.y; acc.z += v.z; acc.w += v.w;
        }
    } else {
        #pragma unroll
        for (int l = 0; l < LL; l++) {
            int id = ids32[base + l];
            float4 v = __ldg(&emb[(long)id * 4 + lane]);
            acc.x += v.x; acc.y += v.y; acc.z += v.z; acc.w += v.w;
        }
    }
    int fb = f * DD + lane * 4;
    g_xT[(fb + 0) * BATCH + b] = acc.x;
    g_xT[(fb + 1) * BATCH + b] = acc.y;
    g_xT[(fb + 2) * BATCH + b] = acc.z;
    g_xT[(fb + 3) * BATCH + b] = acc.w;
}

// ---------------------------------------------------------------------------
// Kernel B: experts GEMM  expT[c][b] = relu( sum_k xT[k][b] * W[e][k][s] + eb )
// Block tile 64 rows x 128 cols; thread tile 4 rows x 8 cols (4x4 f32x2 accs).
// Weights pre-packed in smem as ws2[k][j][tx] so LDS is conflict-free.
// ---------------------------------------------------------------------------
__global__ __launch_bounds__(256) void expert_kernel(const float* __restrict__ ew,
                                                     const float* __restrict__ eb) {
    __shared__ u64 xs2[16][64];       // x duplicated pairs: (x,x) per row
    __shared__ u64 ws2[16][4][16];    // packed weight pairs, lane-major

    int tid = threadIdx.x;
    int tx  = tid & 15;
    int ty  = tid >> 4;
    int b0  = blockIdx.x * 64;
    int c0  = blockIdx.y * 128;

    u64 acc[4][4];
    #pragma unroll
    for (int r = 0; r < 4; r++)
        #pragma unroll
        for (int j = 0; j < 4; j++) acc[r][j] = 0ull;

    for (int k0 = 0; k0 < FEAT; k0 += 16) {
        __syncthreads();
        #pragma unroll
        for (int i = tid; i < 16 * 64; i += 256) {
            int k = i >> 6, r = i & 63;
            float v = g_xT[(k0 + k) * BATCH + b0 + r];
            xs2[k][r] = pack2(v, v);
        }
        #pragma unroll
        for (int i = tid; i < 16 * 64; i += 256) {
            int k = i >> 6, q = i & 63;
            int j = q >> 4, tl = q & 15;
            int c = c0 + tl * 8 + 2 * j;
            int e = c >> 6, s = c & 63;
            const float* p = &ew[(long)(e * FEAT + k0 + k) * SS + s];
            ws2[k][j][tl] = pack2(p[0], p[1]);
        }
        __syncthreads();
        #pragma unroll
        for (int k = 0; k < 16; k++) {
            u64 w0 = ws2[k][0][tx];
            u64 w1 = ws2[k][1][tx];
            u64 w2 = ws2[k][2][tx];
            u64 w3 = ws2[k][3][tx];
            ulonglong2 x01 = *(const ulonglong2*)&xs2[k][ty * 4];
            ulonglong2 x23 = *(const ulonglong2*)&xs2[k][ty * 4 + 2];
            acc[0][0] = ffma2(x01.x, w0, acc[0][0]);
            acc[0][1] = ffma2(x01.x, w1, acc[0][1]);
            acc[0][2] = ffma2(x01.x, w2, acc[0][2]);
            acc[0][3] = ffma2(x01.x, w3, acc[0][3]);
            acc[1][0] = ffma2(x01.y, w0, acc[1][0]);
            acc[1][1] = ffma2(x01.y, w1, acc[1][1]);
            acc[1][2] = ffma2(x01.y, w2, acc[1][2]);
            acc[1][3] = ffma2(x01.y, w3, acc[1][3]);
            acc[2][0] = ffma2(x23.x, w0, acc[2][0]);
            acc[2][1] = ffma2(x23.x, w1, acc[2][1]);
            acc[2][2] = ffma2(x23.x, w2, acc[2][2]);
            acc[2][3] = ffma2(x23.x, w3, acc[2][3]);
            acc[3][0] = ffma2(x23.y, w0, acc[3][0]);
            acc[3][1] = ffma2(x23.y, w1, acc[3][1]);
            acc[3][2] = ffma2(x23.y, w2, acc[3][2]);
            acc[3][3] = ffma2(x23.y, w3, acc[3][3]);
        }
    }

    // Epilogue: bias + relu, float4 store over 4 consecutive rows per column.
    #pragma unroll
    for (int j = 0; j < 4; j++) {
        int c = c0 + tx * 8 + 2 * j;
        int e = c >> 6, s = c & 63;
        float bL = eb[e * SS + s];
        float bH = eb[e * SS + s + 1];
        float lo[4], hi[4];
        #pragma unroll
        for (int r = 0; r < 4; r++) unpack2(acc[r][j], lo[r], hi[r]);
        float4 vL = make_float4(fmaxf(lo[0] + bL, 0.f), fmaxf(lo[1] + bL, 0.f),
                                fmaxf(lo[2] + bL, 0.f), fmaxf(lo[3] + bL, 0.f));
        float4 vH = make_float4(fmaxf(hi[0] + bH, 0.f), fmaxf(hi[1] + bH, 0.f),
                                fmaxf(hi[2] + bH, 0.f), fmaxf(hi[3] + bH, 0.f));
        *(float4*)&g_expT[(long)c       * BATCH + b0 + ty * 4] = vL;
        *(float4*)&g_expT[(long)(c + 1) * BATCH + b0 + ty * 4] = vH;
    }
}

// ---------------------------------------------------------------------------
// Kernel C: gates softmax + mix + tower + out heads + epilogue. 1 thread = 1 row.
// ---------------------------------------------------------------------------
__global__ __launch_bounds__(64) void head_kernel(const float* __restrict__ gw,
                                                  const float* __restrict__ gb,
                                                  const float* __restrict__ tw,
                                                  const float* __restrict__ tb,
                                                  const float* __restrict__ ow,
                                                  const float* __restrict__ ob,
                                                  float* __restrict__ out) {
    __shared__ u64   s_gw[FEAT][12];   // gate_w pairs over e: [f][g*4+e2]
    __shared__ u64   s_tw[SS][48];     // tower_w pairs over t: [s][g*16+t2]
    __shared__ float s_ow[NG * TT * 2];
    __shared__ float s_tb[NG * TT];
    __shared__ float s_ob[NG * 2];
    __shared__ float s_gb[NG * NE];

    int tid = threadIdx.x;
    for (int i = tid; i < FEAT * 12; i += 64) {
        int f = i / 12, j = i % 12;
        int g = j >> 2, e2 = j & 3;
        const float* p = &gw[(long)(g * FEAT + f) * NE + 2 * e2];
        s_gw[f][j] = pack2(p[0], p[1]);
    }
    for (int i = tid; i < SS * 48; i += 64) {
        int s = i / 48, j = i % 48;
        int g = j >> 4, t2 = j & 15;
        const float* p = &tw[(long)(g * SS + s) * TT + 2 * t2];
        s_tw[s][j] = pack2(p[0], p[1]);
    }
    for (int i = tid; i < NG * TT * 2; i += 64) s_ow[i] = ow[i];
    for (int i = tid; i < NG * TT; i += 64)     s_tb[i] = tb[i];
    if (tid < NG * 2)  s_ob[tid] = ob[tid];
    if (tid < NG * NE) s_gb[tid] = gb[tid];
    __syncthreads();

    int b = blockIdx.x * 64 + tid;

    // --- gate logits ---
    u64 gl[12];
    #pragma unroll
    for (int j = 0; j < 12; j++) {
        int g = j >> 2, e2 = j & 3;
        gl[j] = pack2(s_gb[g * NE + 2 * e2], s_gb[g * NE + 2 * e2 + 1]);
    }
    #pragma unroll 4
    for (int k = 0; k < FEAT; k++) {
        float x = g_xT[k * BATCH + b];
        u64 xv = pack2(x, x);
        #pragma unroll
        for (int j = 0; j < 12; j++) gl[j] = ffma2(xv, s_gw[k][j], gl[j]);
    }

    // --- gate softmax (over E=8) ---
    float gate[NG][NE];
    #pragma unroll
    for (int g = 0; g < NG; g++) {
        float lg[NE];
        #pragma unroll
        for (int e2 = 0; e2 < 4; e2++) unpack2(gl[g * 4 + e2], lg[2 * e2], lg[2 * e2 + 1]);
        float m = lg[0];
        #pragma unroll
        for (int e = 1; e < NE; e++) m = fmaxf(m, lg[e]);
        float sum = 0.f;
        #pragma unroll
        for (int e = 0; e < NE; e++) { lg[e] = expf(lg[e] - m); sum += lg[e]; }
        float inv = 1.f / sum;
        #pragma unroll
        for (int e = 0; e < NE; e++) gate[g][e] = lg[e] * inv;
    }

    // --- mix + tower (fold mix[g][s] immediately into tower accumulators) ---
    u64 ta[48];
    #pragma unroll
    for (int j = 0; j < 48; j++) {
        int g = j >> 4, t2 = j & 15;
        ta[j] = pack2(s_tb[g * TT + 2 * t2], s_tb[g * TT + 2 * t2 + 1]);
    }
    #pragma unroll 2
    for (int s = 0; s < SS; s++) {
        float v[NE];
        #pragma unroll
        for (int e = 0; e < NE; e++) v[e] = g_expT[(long)(e * SS + s) * BATCH + b];
        #pragma unroll
        for (int g = 0; g < NG; g++) {
            float m = 0.f;
            #pragma unroll
            for (int e = 0; e < NE; e++) m = fmaf(gate[g][e], v[e], m);
            u64 m2 = pack2(m, m);
            #pragma unroll
            for (int t2 = 0; t2 < 16; t2++)
                ta[g * 16 + t2] = ffma2(m2, s_tw[s][g * 16 + t2], ta[g * 16 + t2]);
        }
    }

    // --- tower relu, out heads, softmax(2), clip, epilogue ---
    float ctr0 = 0.f, ctr1 = 0.f, cvr0 = 0.f, cvr1 = 0.f, imp1 = 0.f;
    #pragma unroll
    for (int g = 0; g < NG; g++) {
        float l0 = s_ob[g * 2 + 0], l1 = s_ob[g * 2 + 1];
        #pragma unroll
        for (int t2 = 0; t2 < 16; t2++) {
            float a, c;
            unpack2(ta[g * 16 + t2], a, c);
            a = fmaxf(a, 0.f); c = fmaxf(c, 0.f);
            l0 = fmaf(a, s_ow[(g * TT + 2 * t2) * 2 + 0], l0);
            l1 = fmaf(a, s_ow[(g * TT + 2 * t2) * 2 + 1], l1);
            l0 = fmaf(c, s_ow[(g * TT + 2 * t2 + 1) * 2 + 0], l0);
            l1 = fmaf(c, s_ow[(g * TT + 2 * t2 + 1) * 2 + 1], l1);
        }
        float mm = fmaxf(l0, l1);
        float e0 = expf(l0 - mm), e1 = expf(l1 - mm);
        float inv = 1.f / (e0 + e1);
        float p0 = fminf(fmaxf(e0 * inv, 1e-15f), 1.f - 1e-15f);
        float p1 = fminf(fmaxf(e1 * inv, 1e-15f), 1.f - 1e-15f);
        if (g == 0)      { ctr0 = p0; ctr1 = p1; }
        else if (g == 1) { cvr0 = p0; cvr1 = p1; }
        else             { imp1 = p1; }
    }
    float cc = ctr1 * cvr1;
    float* o = out + (long)b * 10;
    o[0] = ctr0; o[1] = ctr1; o[2] = ctr1;
    o[3] = cvr0; o[4] = cvr1; o[5] = cvr1;
    o[6] = 1.f - cc; o[7] = cc; o[8] = cc;
    o[9] = imp1;
}

extern "C" void kernel_launch(void* const* d_in, const int* in_sizes, int n_in,
                              void* d_out, int out_size) {
    const int*   ids = (const int*)d_in[0];
    const float* emb = (const float*)d_in[1];
    const float* ew  = (const float*)d_in[2];
    const float* eb  = (const float*)d_in[3];
    const float* gw  = (const float*)d_in[4];
    const float* gb  = (const float*)d_in[5];
    const float* tw  = (const float*)d_in[6];
    const float* tb  = (const float*)d_in[7];
    const float* ow  = (const float*)d_in[8];
    const float* ob  = (const float*)d_in[9];
    float* out = (float*)d_out;

    gather_kernel<<<(NF * BATCH) / 64, 256>>>(ids, (const float4*)emb);
    expert_kernel<<<dim3(BATCH / 64, NCOLS / 128), 256>>>(ew, eb);
    head_kernel<<<BATCH / 64, 64>>>(gw, gb, tw, tb, ow, ob, out);
}

// round 2
// speedup vs baseline: 1.0602x; 1.0602x over previous
#include <cuda_runtime.h>
#include <math.h>

typedef unsigned long long u64;

#define BATCH 16384
#define NF 10
#define LL 20
#define DD 16
#define FEAT 160
#define NE 8
#define SS 64
#define NG 3
#define TT 32
#define NCOLS (NE*SS)

// Scratch (device globals: no allocation allowed)
__device__ __align__(16) float g_xT[FEAT * BATCH];   // x transposed: [feat][b]  (for expert GEMM)
__device__ __align__(16) float g_x [BATCH * FEAT];   // x natural:    [b][feat]  (for head)
__device__ __align__(16) float g_exp[BATCH * NCOLS]; // experts natural: [b][e*64+s]

__device__ __forceinline__ u64 pack2(float lo, float hi) {
    u64 d;
    asm("mov.b64 %0, {%1, %2};" : "=l"(d)
        : "r"(__float_as_uint(lo)), "r"(__float_as_uint(hi)));
    return d;
}
__device__ __forceinline__ void unpack2(u64 v, float &lo, float &hi) {
    unsigned a, b;
    asm("mov.b64 {%0, %1}, %2;" : "=r"(a), "=r"(b) : "l"(v));
    lo = __uint_as_float(a); hi = __uint_as_float(b);
}
__device__ __forceinline__ u64 ffma2(u64 a, u64 b, u64 c) {
    u64 d;
    asm("fma.rn.f32x2 %0, %1, %2, %3;" : "=l"(d) : "l"(a), "l"(b), "l"(c));
    return d;
}
__device__ __forceinline__ u64 fadd2(u64 a, u64 b) {
    u64 d;
    asm("add.rn.f32x2 %0, %1, %2;" : "=l"(d) : "l"(a), "l"(b));
    return d;
}

// ---------------------------------------------------------------------------
// Kernel A: embedding gather + sum over L; writes BOTH xT[feat][b] and x[b][feat].
// 4 lanes per (f,b) pair; each lane owns 4 of the 16 embedding dims (float4).
// ---------------------------------------------------------------------------
__global__ __launch_bounds__(256) void gather_kernel(const int* __restrict__ ids32,
                                                     const float4* __restrict__ emb) {
    __shared__ int s_is64;
    if (threadIdx.x == 0) {
        const unsigned* w = (const unsigned*)ids32;
        s_is64 = (w[1] == 0u && w[3] == 0u && w[5] == 0u && w[7] == 0u) ? 1 : 0;
    }
    __syncthreads();
    const int is64 = s_is64;

    int tid  = threadIdx.x;
    int p    = blockIdx.x * 64 + (tid >> 2);  // p = f*BATCH + b
    int lane = tid & 3;
    int f = p >> 14;
    int b = p & (BATCH - 1);
    long base = (long)p * LL;

    float4 acc = make_float4(0.f, 0.f, 0.f, 0.f);
    if (is64) {
        #pragma unroll
        for (int l = 0; l < LL; l++) {
            int id = ids32[2 * (base + l)];       // low word of int64
            float4 v = __ldg(&emb[(long)id * 4 + lane]);
            acc.x += v.x; acc.y += v.y; acc.z += v.z; acc.w += v.w;
        }
    } else {
        #pragma unroll
        for (int l = 0; l < LL; l++) {
            int id = ids32[base + l];
            float4 v = __ldg(&emb[(long)id * 4 + lane]);
            acc.x += v.x; acc.y += v.y; acc.z += v.z; acc.w += v.w;
        }
    }
    int fb = f * DD + lane * 4;
    g_xT[(fb + 0) * BATCH + b] = acc.x;
    g_xT[(fb + 1) * BATCH + b] = acc.y;
    g_xT[(fb + 2) * BATCH + b] = acc.z;
    g_xT[(fb + 3) * BATCH + b] = acc.w;
    *(float4*)&g_x[(long)b * FEAT + fb] = acc;
}

// ---------------------------------------------------------------------------
// Kernel B: experts GEMM  exp[b][c] = relu( sum_k xT[k][b] * W[e][k][s] + eb )
// Block tile 64 rows x 128 cols; thread tile 4 rows x 8 cols (4x4 f32x2 accs).
// Register-prefetch double buffering: one __syncthreads per k-tile.
// ---------------------------------------------------------------------------
__global__ __launch_bounds__(256) void expert_kernel(const float* __restrict__ ew,
                                                     const float* __restrict__ eb) {
    __shared__ u64 xs2[2][16][64];    // x duplicated pairs: (x,x) per row
    __shared__ u64 ws2[2][16][64];    // packed weight pairs, flat q = j*16 + tl

    int tid = threadIdx.x;
    int tx  = tid & 15;
    int ty  = tid >> 4;
    int b0  = blockIdx.x * 64;
    int c0  = blockIdx.y * 128;

    // Fixed per-thread fill coordinates: i = tid + 256n -> k = (tid>>6)+4n, pos = tid&63
    int kb  = tid >> 6;
    int pos = tid & 63;
    int jq  = pos >> 4;          // weight j
    int tlq = pos & 15;          // weight lane
    int cw  = c0 + tlq * 8 + 2 * jq;
    int eW  = cw >> 6, sW = cw & 63;

    u64 acc[4][4];
    #pragma unroll
    for (int r = 0; r < 4; r++)
        #pragma unroll
        for (int j = 0; j < 4; j++) acc[r][j] = 0ull;

    float  xv[4];
    float2 wv[4];

    // prefetch tile 0
    #pragma unroll
    for (int n = 0; n < 4; n++) {
        int k = kb + 4 * n;
        xv[n] = g_xT[(long)k * BATCH + b0 + pos];
        wv[n] = *(const float2*)&ew[(long)(eW * FEAT + k) * SS + sW];
    }
    #pragma unroll
    for (int n = 0; n < 4; n++) {
        int k = kb + 4 * n;
        xs2[0][k][pos] = pack2(xv[n], xv[n]);
        ws2[0][k][pos] = pack2(wv[n].x, wv[n].y);
    }
    __syncthreads();

    #pragma unroll 1
    for (int t = 0; t < 10; t++) {
        int cur = t & 1;
        if (t < 9) {
            int k0n = (t + 1) * 16;
            #pragma unroll
            for (int n = 0; n < 4; n++) {
                int k = k0n + kb + 4 * n;
                xv[n] = g_xT[(long)k * BATCH + b0 + pos];
                wv[n] = *(const float2*)&ew[(long)(eW * FEAT + k) * SS + sW];
            }
        }
        #pragma unroll
        for (int k = 0; k < 16; k++) {
            u64 w0 = ws2[cur][k][(0 << 4) | tx];
            u64 w1 = ws2[cur][k][(1 << 4) | tx];
            u64 w2 = ws2[cur][k][(2 << 4) | tx];
            u64 w3 = ws2[cur][k][(3 << 4) | tx];
            ulonglong2 x01 = *(const ulonglong2*)&xs2[cur][k][ty * 4];
            ulonglong2 x23 = *(const ulonglong2*)&xs2[cur][k][ty * 4 + 2];
            acc[0][0] = ffma2(x01.x, w0, acc[0][0]);
            acc[0][1] = ffma2(x01.x, w1, acc[0][1]);
            acc[0][2] = ffma2(x01.x, w2, acc[0][2]);
            acc[0][3] = ffma2(x01.x, w3, acc[0][3]);
            acc[1][0] = ffma2(x01.y, w0, acc[1][0]);
            acc[1][1] = ffma2(x01.y, w1, acc[1][1]);
            acc[1][2] = ffma2(x01.y, w2, acc[1][2]);
            acc[1][3] = ffma2(x01.y, w3, acc[1][3]);
            acc[2][0] = ffma2(x23.x, w0, acc[2][0]);
            acc[2][1] = ffma2(x23.x, w1, acc[2][1]);
            acc[2][2] = ffma2(x23.x, w2, acc[2][2]);
            acc[2][3] = ffma2(x23.x, w3, acc[2][3]);
            acc[3][0] = ffma2(x23.y, w0, acc[3][0]);
            acc[3][1] = ffma2(x23.y, w1, acc[3][1]);
            acc[3][2] = ffma2(x23.y, w2, acc[3][2]);
            acc[3][3] = ffma2(x23.y, w3, acc[3][3]);
        }
        if (t < 9) {
            int nxt = cur ^ 1;
            #pragma unroll
            for (int n = 0; n < 4; n++) {
                int k = kb + 4 * n;
                xs2[nxt][k][pos] = pack2(xv[n], xv[n]);
                ws2[nxt][k][pos] = pack2(wv[n].x, wv[n].y);
            }
        }
        __syncthreads();
    }

    // Epilogue: bias + relu; natural layout, 2x float4 per row (8 contiguous cols).
    int cbase = c0 + tx * 8;
    int e = cbase >> 6;
    float bias[8];
    #pragma unroll
    for (int cc = 0; cc < 8; cc++) bias[cc] = eb[e * SS + ((cbase + cc) & 63)];
    #pragma unroll
    for (int r = 0; r < 4; r++) {
        int b = b0 + ty * 4 + r;
        float v[8];
        #pragma unroll
        for (int j = 0; j < 4; j++) unpack2(acc[r][j], v[2 * j], v[2 * j + 1]);
        float4 o0 = make_float4(fmaxf(v[0] + bias[0], 0.f), fmaxf(v[1] + bias[1], 0.f),
                                fmaxf(v[2] + bias[2], 0.f), fmaxf(v[3] + bias[3], 0.f));
        float4 o1 = make_float4(fmaxf(v[4] + bias[4], 0.f), fmaxf(v[5] + bias[5], 0.f),
                                fmaxf(v[6] + bias[6], 0.f), fmaxf(v[7] + bias[7], 0.f));
        *(float4*)&g_exp[(long)b * NCOLS + cbase]     = o0;
        *(float4*)&g_exp[(long)b * NCOLS + cbase + 4] = o1;
    }
}

// ---------------------------------------------------------------------------
// Kernel C: gates softmax + mix + tower + out heads + epilogue.
// 2 threads per row (half h in {0,1}); k-range split for gates, s-range split
// for mix/tower; f32x2 reductions through shared memory.
// ---------------------------------------------------------------------------
struct HeadSmem {
    u64   gw[FEAT][12];   // gate_w pairs over e:  [f][g*4+e2]     15360 B
    u64   tw[SS][48];     // tower_w pairs over t: [s][g*16+t2]    24576 B
    u64   red[64][48];    // reduction buffer (gl, gates, ta)      24576 B
    float ow[NG * TT * 2];
    float tb[NG * TT];
    float gb[NG * NE];
    float ob[NG * 2];
};

__global__ __launch_bounds__(128) void head_kernel(const float* __restrict__ gw,
                                                   const float* __restrict__ gb,
                                                   const float* __restrict__ tw,
                                                   const float* __restrict__ tb,
                                                   const float* __restrict__ ow,
                                                   const float* __restrict__ ob,
                                                   float* __restrict__ out) {
    extern __shared__ char smem_raw[];
    HeadSmem* sm = (HeadSmem*)smem_raw;

    int tid = threadIdx.x;
    int bl  = tid & 63;      // local row
    int h   = tid >> 6;      // half: 0 or 1
    int b   = blockIdx.x * 64 + bl;

    // ---- smem fills ----
    for (int i = tid; i < FEAT * 12; i += 128) {
        int f = i / 12, j = i % 12;
        int g = j >> 2, e2 = j & 3;
        float2 p = *(const float2*)&gw[(long)(g * FEAT + f) * NE + 2 * e2];
        sm->gw[f][j] = pack2(p.x, p.y);
    }
    for (int i = tid; i < SS * 48; i += 128) {
        int s = i / 48, j = i % 48;
        int g = j >> 4, t2 = j & 15;
        float2 p = *(const float2*)&tw[(long)(g * SS + s) * TT + 2 * t2];
        sm->tw[s][j] = pack2(p.x, p.y);
    }
    for (int i = tid; i < NG * TT * 2; i += 128) sm->ow[i] = ow[i];
    if (tid < NG * TT) sm->tb[tid] = tb[tid];
    if (tid < NG * NE) sm->gb[tid] = gb[tid];
    if (tid < NG * 2)  sm->ob[tid] = ob[tid];
    __syncthreads();

    // ---- gate logits: half h covers k in [h*80, h*80+80) ----
    u64 gl[12];
    #pragma unroll
    for (int j = 0; j < 12; j++) {
        if (h == 0) {
            int g = j >> 2, e2 = j & 3;
            gl[j] = pack2(sm->gb[g * NE + 2 * e2], sm->gb[g * NE + 2 * e2 + 1]);
        } else gl[j] = 0ull;
    }
    {
        const float4* xp = (const float4*)&g_x[(long)b * FEAT + h * 80];
        #pragma unroll 5
        for (int kk = 0; kk < 20; kk++) {
            float4 x4 = xp[kk];
            int kbase = h * 80 + kk * 4;
            float xs[4] = {x4.x, x4.y, x4.z, x4.w};
            #pragma unroll
            for (int c = 0; c < 4; c++) {
                u64 xv = pack2(xs[c], xs[c]);
                const ulonglong2* gwrow = (const ulonglong2*)&sm->gw[kbase + c][0];
                #pragma unroll
                for (int q = 0; q < 6; q++) {
                    ulonglong2 wp = gwrow[q];
                    gl[2 * q]     = ffma2(xv, wp.x, gl[2 * q]);
                    gl[2 * q + 1] = ffma2(xv, wp.y, gl[2 * q + 1]);
                }
            }
        }
    }

    // ---- reduce gate logits, softmax (h==0), publish gates ----
    if (h == 1) {
        #pragma unroll
        for (int j = 0; j < 12; j++) sm->red[bl][j] = gl[j];
    }
    __syncthreads();
    if (h == 0) {
        float* gout = (float*)&sm->red[bl][0];
        #pragma unroll
        for (int g = 0; g < NG; g++) {
            float lg[NE];
            #pragma unroll
            for (int e2 = 0; e2 < 4; e2++) {
                u64 v = fadd2(gl[g * 4 + e2], sm->red[bl][g * 4 + e2]);
                unpack2(v, lg[2 * e2], lg[2 * e2 + 1]);
            }
            float m = lg[0];
            #pragma unroll
            for (int e = 1; e < NE; e++) m = fmaxf(m, lg[e]);
            float sum = 0.f;
            #pragma unroll
            for (int e = 0; e < NE; e++) { lg[e] = __expf(lg[e] - m); sum += lg[e]; }
            float inv = __fdividef(1.f, sum);
            #pragma unroll
            for (int e = 0; e < NE; e++) gout[g * NE + e] = lg[e] * inv;
        }
    }
    __syncthreads();
    float gate[NG][NE];
    {
        const float* gin = (const float*)&sm->red[bl][0];
        #pragma unroll
        for (int g = 0; g < NG; g++)
            #pragma unroll
            for (int e = 0; e < NE; e++) gate[g][e] = gin[g * NE + e];
    }
    __syncthreads();   // everyone has gates before red[] is reused

    // ---- mix + tower partial: half h covers s in [h*32, h*32+32) ----
    u64 ta[48];
    #pragma unroll
    for (int j = 0; j < 48; j++) {
        if (h == 0) {
            int g = j >> 4, t2 = j & 15;
            ta[j] = pack2(sm->tb[g * TT + 2 * t2], sm->tb[g * TT + 2 * t2 + 1]);
        } else ta[j] = 0ull;
    }
    {
        const float* ebase = &g_exp[(long)b * NCOLS];
        #pragma unroll 1
        for (int sc = 0; sc < 8; sc++) {
            int s = h * 32 + sc * 4;
            float4 v[NE];
            #pragma unroll
            for (int e = 0; e < NE; e++)
                v[e] = *(const float4*)&ebase[e * SS + s];
            #pragma unroll
            for (int ss = 0; ss < 4; ss++) {
                float ve[NE];
                #pragma unroll
                for (int e = 0; e < NE; e++)
                    ve[e] = (ss == 0) ? v[e].x : (ss == 1) ? v[e].y : (ss == 2) ? v[e].z : v[e].w;
                u64 m2[NG];
                #pragma unroll
                for (int g = 0; g < NG; g++) {
                    float m = 0.f;
                    #pragma unroll
                    for (int e = 0; e < NE; e++) m = fmaf(gate[g][e], ve[e], m);
                    m2[g] = pack2(m, m);
                }
                const ulonglong2* twrow = (const ulonglong2*)&sm->tw[s + ss][0];
                #pragma unroll
                for (int q = 0; q < 24; q++) {
                    ulonglong2 wp = twrow[q];
                    int g = q >> 3;
                    ta[2 * q]     = ffma2(m2[g], wp.x, ta[2 * q]);
                    ta[2 * q + 1] = ffma2(m2[g], wp.y, ta[2 * q + 1]);
                }
            }
        }
    }

    // ---- reduce tower accumulators, epilogue (h==0) ----
    if (h == 1) {
        #pragma unroll
        for (int j = 0; j < 48; j++) sm->red[bl][j] = ta[j];
    }
    __syncthreads();
    if (h == 0) {
        float ctr0 = 0.f, ctr1 = 0.f, cvr0 = 0.f, cvr1 = 0.f, imp1 = 0.f;
        #pragma unroll
        for (int g = 0; g < NG; g++) {
            float l0 = sm->ob[g * 2 + 0], l1 = sm->ob[g * 2 + 1];
            #pragma unroll
            for (int t2 = 0; t2 < 16; t2++) {
                u64 v = fadd2(ta[g * 16 + t2], sm->red[bl][g * 16 + t2]);
                float a, c;
                unpack2(v, a, c);
                a = fmaxf(a, 0.f); c = fmaxf(c, 0.f);
                l0 = fmaf(a, sm->ow[(g * TT + 2 * t2) * 2 + 0], l0);
                l1 = fmaf(a, sm->ow[(g * TT + 2 * t2) * 2 + 1], l1);
                l0 = fmaf(c, sm->ow[(g * TT + 2 * t2 + 1) * 2 + 0], l0);
                l1 = fmaf(c, sm->ow[(g * TT + 2 * t2 + 1) * 2 + 1], l1);
            }
            float mm = fmaxf(l0, l1);
            float e0 = __expf(l0 - mm), e1 = __expf(l1 - mm);
            float inv = __fdividef(1.f, e0 + e1);
            float p0 = fminf(fmaxf(e0 * inv, 1e-15f), 1.f - 1e-15f);
            float p1 = fminf(fmaxf(e1 * inv, 1e-15f), 1.f - 1e-15f);
            if (g == 0)      { ctr0 = p0; ctr1 = p1; }
            else if (g == 1) { cvr0 = p0; cvr1 = p1; }
            else             { imp1 = p1; }
        }
        float cc = ctr1 * cvr1;
        float* o = out + (long)b * 10;
        o[0] = ctr0; o[1] = ctr1; o[2] = ctr1;
        o[3] = cvr0; o[4] = cvr1; o[5] = cvr1;
        o[6] = 1.f - cc; o[7] = cc; o[8] = cc;
        o[9] = imp1;
    }
}

extern "C" void kernel_launch(void* const* d_in, const int* in_sizes, int n_in,
                              void* d_out, int out_size) {
    const int*   ids = (const int*)d_in[0];
    const float* emb = (const float*)d_in[1];
    const float* ew  = (const float*)d_in[2];
    const float* eb  = (const float*)d_in[3];
    const float* gw  = (const float*)d_in[4];
    const float* gb  = (const float*)d_in[5];
    const float* tw  = (const float*)d_in[6];
    const float* tb  = (const float*)d_in[7];
    const float* ow  = (const float*)d_in[8];
    const float* ob  = (const float*)d_in[9];
    float* out = (float*)d_out;

    static bool attr_set = false;
    if (!attr_set) {
        cudaFuncSetAttribute(head_kernel, cudaFuncAttributeMaxDynamicSharedMemorySize,
                             (int)sizeof(HeadSmem));
        attr_set = true;
    }

    gather_kernel<<<(NF * BATCH) / 64, 256>>>(ids, (const float4*)emb);
    expert_kernel<<<dim3(BATCH / 64, NCOLS / 128), 256>>>(ew, eb);
    head_kernel<<<BATCH / 64, 128, sizeof(HeadSmem)>>>(gw, gb, tw, tb, ow, ob, out);
}

// round 4
// speedup vs baseline: 1.5019x; 1.4166x over previous
#include <cuda_runtime.h>
#include <cuda_bf16.h>
#include <math.h>

typedef unsigned long long u64;
typedef unsigned int u32;

#define BATCH 16384
#define NF 10
#define LL 20
#define DD 16
#define FEAT 160
#define NE 8
#define SS 64
#define NG 3
#define TT 32
#define NCOLS (NE*SS)

#define TM 128
#define TN 128
#define STRIDE 168                      // padded bf16 row stride (336B: 8-row ldmatrix conflict-free)
#define TILE_U16 (128 * STRIDE)        // one bf16 tile in u16 elements
#define DYN_SMEM (4 * TILE_U16 * 2)    // aHi, aLo, bHi, bLo

// Scratch (device globals: no allocation allowed)
__device__ __align__(16) float          g_x  [BATCH * FEAT];   // x fp32 natural [b][f] (head)
__device__ __align__(16) unsigned short g_xhi[BATCH * FEAT];   // bf16 hi
__device__ __align__(16) unsigned short g_xlo[BATCH * FEAT];   // bf16 lo
__device__ __align__(16) unsigned short g_whi[NCOLS * FEAT];   // W^T bf16 hi: [c][k]
__device__ __align__(16) unsigned short g_wlo[NCOLS * FEAT];   // W^T bf16 lo
__device__ __align__(16) float          g_exp[BATCH * NCOLS];  // experts [b][c]

// ---------------- f32x2 helpers (head kernel) ----------------
__device__ __forceinline__ u64 pack2(float lo, float hi) {
    u64 d;
    asm("mov.b64 %0, {%1, %2};" : "=l"(d)
        : "r"(__float_as_uint(lo)), "r"(__float_as_uint(hi)));
    return d;
}
__device__ __forceinline__ void unpack2(u64 v, float &lo, float &hi) {
    unsigned a, b;
    asm("mov.b64 {%0, %1}, %2;" : "=r"(a), "=r"(b) : "l"(v));
    lo = __uint_as_float(a); hi = __uint_as_float(b);
}
__device__ __forceinline__ u64 ffma2(u64 a, u64 b, u64 c) {
    u64 d;
    asm("fma.rn.f32x2 %0, %1, %2, %3;" : "=l"(d) : "l"(a), "l"(b), "l"(c));
    return d;
}
__device__ __forceinline__ u64 fadd2(u64 a, u64 b) {
    u64 d;
    asm("add.rn.f32x2 %0, %1, %2;" : "=l"(d) : "l"(a), "l"(b));
    return d;
}

// ---------------- mma.sync helpers (portable sm_80+ PTX) ----------------
__device__ __forceinline__ u32 smem_u32(const void* p) {
    u32 a;
    asm("{ .reg .u64 t; cvta.to.shared.u64 t, %1; cvt.u32.u64 %0, t; }" : "=r"(a) : "l"(p));
    return a;
}
__device__ __forceinline__ void ldsm4(u32 addr, u32 &r0, u32 &r1, u32 &r2, u32 &r3) {
    asm volatile("ldmatrix.sync.aligned.m8n8.x4.shared.b16 {%0,%1,%2,%3}, [%4];"
                 : "=r"(r0), "=r"(r1), "=r"(r2), "=r"(r3) : "r"(addr));
}
__device__ __forceinline__ void mma16816(float* d, const u32* a, const u32* b) {
    asm volatile("mma.sync.aligned.m16n8k16.row.col.f32.bf16.bf16.f32 "
                 "{%0,%1,%2,%3}, {%4,%5,%6,%7}, {%8,%9}, {%0,%1,%2,%3};"
                 : "+f"(d[0]), "+f"(d[1]), "+f"(d[2]), "+f"(d[3])
                 : "r"(a[0]), "r"(a[1]), "r"(a[2]), "r"(a[3]), "r"(b[0]), "r"(b[1]));
}

// ---------------------------------------------------------------------------
// Kernel A: embedding gather + sum; emits x fp32 [b][f] and bf16 hi/lo splits.
// ---------------------------------------------------------------------------
__global__ __launch_bounds__(256) void gather_kernel(const int* __restrict__ ids32,
                                                     const float4* __restrict__ emb) {
    __shared__ int s_is64;
    if (threadIdx.x == 0) {
        const unsigned* w = (const unsigned*)ids32;
        s_is64 = (w[1] == 0u && w[3] == 0u && w[5] == 0u && w[7] == 0u) ? 1 : 0;
    }
    __syncthreads();
    const int is64 = s_is64;

    int tid  = threadIdx.x;
    int p    = blockIdx.x * 64 + (tid >> 2);  // p = f*BATCH + b
    int lane = tid & 3;
    int f = p >> 14;
    int b = p & (BATCH - 1);
    long base = (long)p * LL;

    float4 acc = make_float4(0.f, 0.f, 0.f, 0.f);
    if (is64) {
        #pragma unroll
        for (int l = 0; l < LL; l++) {
            int id = ids32[2 * (base + l)];
            float4 v = __ldg(&emb[(long)id * 4 + lane]);
            acc.x += v.x; acc.y += v.y; acc.z += v.z; acc.w += v.w;
        }
    } else {
        #pragma unroll
        for (int l = 0; l < LL; l++) {
            int id = ids32[base + l];
            float4 v = __ldg(&emb[(long)id * 4 + lane]);
            acc.x += v.x; acc.y += v.y; acc.z += v.z; acc.w += v.w;
        }
    }
    int fb = f * DD + lane * 4;
    long xoff = (long)b * FEAT + fb;
    *(float4*)&g_x[xoff] = acc;

    float vals[4] = {acc.x, acc.y, acc.z, acc.w};
    unsigned short hi[4], lo[4];
    #pragma unroll
    for (int j = 0; j < 4; j++) {
        __nv_bfloat16 h = __float2bfloat16_rn(vals[j]);
        float r = vals[j] - __bfloat162float(h);
        __nv_bfloat16 l = __float2bfloat16_rn(r);
        hi[j] = *(unsigned short*)&h;
        lo[j] = *(unsigned short*)&l;
    }
    *(uint2*)&g_xhi[xoff] = make_uint2((u32)hi[0] | ((u32)hi[1] << 16),
                                       (u32)hi[2] | ((u32)hi[3] << 16));
    *(uint2*)&g_xlo[xoff] = make_uint2((u32)lo[0] | ((u32)lo[1] << 16),
                                       (u32)lo[2] | ((u32)lo[3] << 16));
}

// ---------------------------------------------------------------------------
// Kernel W: weight transpose + bf16 hi/lo split:  g_w*[c][k] = ew[e][k][s]
// ---------------------------------------------------------------------------
__global__ __launch_bounds__(256) void wprep_kernel(const float* __restrict__ ew) {
    int idx = blockIdx.x * 256 + threadIdx.x;     // 0 .. 512*160-1
    if (idx >= NCOLS * FEAT) return;
    int c = idx & (NCOLS - 1);                    // consecutive tid -> consecutive c
    int k = idx >> 9;
    int e = c >> 6, s = c & 63;
    float w = ew[((long)e * FEAT + k) * SS + s];
    __nv_bfloat16 h = __float2bfloat16_rn(w);
    float r = w - __bfloat162float(h);
    __nv_bfloat16 l = __float2bfloat16_rn(r);
    g_whi[(long)c * FEAT + k] = *(unsigned short*)&h;
    g_wlo[(long)c * FEAT + k] = *(unsigned short*)&l;
}

// ---------------------------------------------------------------------------
// Kernel B: experts GEMM on mma.sync (bf16 3-term split, fp32 accumulate).
// CTA tile 128x128, K=160 fully SMEM-resident. 8 warps as 4(M) x 2(N),
// warp tile 32x64. ldmatrix.x4 fragment loads, conflict-free via STRIDE=168.
// ---------------------------------------------------------------------------
__global__ __launch_bounds__(256) void expert_mma_kernel(const float* __restrict__ eb) {
    extern __shared__ unsigned short sm16[];
    unsigned short* sAhi = sm16;
    unsigned short* sAlo = sm16 + TILE_U16;
    unsigned short* sBhi = sm16 + 2 * TILE_U16;
    unsigned short* sBlo = sm16 + 3 * TILE_U16;
    __shared__ float s_bias[TN];

    int tid  = threadIdx.x;
    int wid  = tid >> 5;
    int lane = tid & 31;
    int b0   = blockIdx.x * TM;
    int c0   = blockIdx.y * TN;

    if (tid < TN) {
        int c = c0 + tid;
        s_bias[tid] = eb[(c >> 6) * SS + (c & 63)];
    }

    // Fill SMEM: 128 rows x 20 uint4-chunks (320B data per row, 336B stride).
    #pragma unroll
    for (int it = 0; it < 10; it++) {
        int idx = tid + it * 256;
        int row = idx / 20;
        int ch  = idx % 20;
        long ga = (long)(b0 + row) * FEAT + ch * 8;
        u32 so  = (u32)(row * STRIDE + ch * 8);
        *(uint4*)&sAhi[so] = *(const uint4*)&g_xhi[ga];
        *(uint4*)&sAlo[so] = *(const uint4*)&g_xlo[ga];
    }
    #pragma unroll
    for (int it = 0; it < 10; it++) {
        int idx = tid + it * 256;
        int row = idx / 20;
        int ch  = idx % 20;
        long ga = (long)(c0 + row) * FEAT + ch * 8;
        u32 so  = (u32)(row * STRIDE + ch * 8);
        *(uint4*)&sBhi[so] = *(const uint4*)&g_whi[ga];
        *(uint4*)&sBlo[so] = *(const uint4*)&g_wlo[ga];
    }
    __syncthreads();

    int m0 = (wid >> 1) * 32;   // warp M origin within tile
    int n0 = (wid & 1) * 64;    // warp N origin within tile

    // ldmatrix per-lane offsets (in bf16 elements)
    u32 aOff = (u32)((m0 + (lane & 7) + ((lane & 8) ? 8 : 0)) * STRIDE + ((lane & 16) ? 8 : 0));
    u32 bOff = (u32)((n0 + (lane & 7) + ((lane & 16) ? 8 : 0)) * STRIDE + ((lane & 8) ? 8 : 0));

    u32 aHiB = smem_u32(sAhi) + aOff * 2;
    u32 aLoB = smem_u32(sAlo) + aOff * 2;
    u32 bHiB = smem_u32(sBhi) + bOff * 2;
    u32 bLoB = smem_u32(sBlo) + bOff * 2;

    float acc[2][8][4];
    #pragma unroll
    for (int mt = 0; mt < 2; mt++)
        #pragma unroll
        for (int nt = 0; nt < 8; nt++)
            #pragma unroll
            for (int q = 0; q < 4; q++) acc[mt][nt][q] = 0.f;

    #pragma unroll
    for (int ks = 0; ks < 10; ks++) {
        u32 kb = (u32)(ks * 16 * 2);   // byte offset along k

        u32 ah[2][4], al[2][4];
        #pragma unroll
        for (int mt = 0; mt < 2; mt++) {
            u32 moff = (u32)(mt * 16 * STRIDE * 2);
            ldsm4(aHiB + moff + kb, ah[mt][0], ah[mt][1], ah[mt][2], ah[mt][3]);
            ldsm4(aLoB + moff + kb, al[mt][0], al[mt][1], al[mt][2], al[mt][3]);
        }
        u32 bh[4][4], blo[4][4];
        #pragma unroll
        for (int nt2 = 0; nt2 < 4; nt2++) {
            u32 noff = (u32)(nt2 * 16 * STRIDE * 2);
            ldsm4(bHiB + noff + kb, bh[nt2][0], bh[nt2][1], bh[nt2][2], bh[nt2][3]);
            ldsm4(bLoB + noff + kb, blo[nt2][0], blo[nt2][1], blo[nt2][2], blo[nt2][3]);
        }

        #pragma unroll
        for (int mt = 0; mt < 2; mt++) {
            #pragma unroll
            for (int nt2 = 0; nt2 < 4; nt2++) {
                mma16816(acc[mt][2 * nt2],     ah[mt], &bh[nt2][0]);
                mma16816(acc[mt][2 * nt2 + 1], ah[mt], &bh[nt2][2]);
                mma16816(acc[mt][2 * nt2],     ah[mt], &blo[nt2][0]);
                mma16816(acc[mt][2 * nt2 + 1], ah[mt], &blo[nt2][2]);
                mma16816(acc[mt][2 * nt2],     al[mt], &bh[nt2][0]);
                mma16816(acc[mt][2 * nt2 + 1], al[mt], &bh[nt2][2]);
            }
        }
    }

    // Epilogue: bias + relu, float2 stores.
    #pragma unroll
    for (int mt = 0; mt < 2; mt++) {
        int row = b0 + m0 + mt * 16 + (lane >> 2);
        #pragma unroll
        for (int nt = 0; nt < 8; nt++) {
            int cl = n0 + nt * 8 + (lane & 3) * 2;   // col within tile
            float bi0 = s_bias[cl], bi1 = s_bias[cl + 1];
            float* d = acc[mt][nt];
            *(float2*)&g_exp[(long)row * NCOLS + c0 + cl] =
                make_float2(fmaxf(d[0] + bi0, 0.f), fmaxf(d[1] + bi1, 0.f));
            *(float2*)&g_exp[(long)(row + 8) * NCOLS + c0 + cl] =
                make_float2(fmaxf(d[2] + bi0, 0.f), fmaxf(d[3] + bi1, 0.f));
        }
    }
}

// ---------------------------------------------------------------------------
// Kernel C: gates softmax + mix + tower + out heads + epilogue (2 thr / row).
// ---------------------------------------------------------------------------
struct HeadSmem {
    u64   gw[FEAT][12];
    u64   tw[SS][48];
    u64   red[64][48];
    float ow[NG * TT * 2];
    float tb[NG * TT];
    float gb[NG * NE];
    float ob[NG * 2];
};

__global__ __launch_bounds__(128) void head_kernel(const float* __restrict__ gw,
                                                   const float* __restrict__ gb,
                                                   const float* __restrict__ tw,
                                                   const float* __restrict__ tb,
                                                   const float* __restrict__ ow,
                                                   const float* __restrict__ ob,
                                                   float* __restrict__ out) {
    extern __shared__ char smem_raw[];
    HeadSmem* sm = (HeadSmem*)smem_raw;

    int tid = threadIdx.x;
    int bl  = tid & 63;
    int h   = tid >> 6;
    int b   = blockIdx.x * 64 + bl;

    for (int i = tid; i < FEAT * 12; i += 128) {
        int f = i / 12, j = i % 12;
        int g = j >> 2, e2 = j & 3;
        float2 p = *(const float2*)&gw[(long)(g * FEAT + f) * NE + 2 * e2];
        sm->gw[f][j] = pack2(p.x, p.y);
    }
    for (int i = tid; i < SS * 48; i += 128) {
        int s = i / 48, j = i % 48;
        int g = j >> 4, t2 = j & 15;
        float2 p = *(const float2*)&tw[(long)(g * SS + s) * TT + 2 * t2];
        sm->tw[s][j] = pack2(p.x, p.y);
    }
    for (int i = tid; i < NG * TT * 2; i += 128) sm->ow[i] = ow[i];
    if (tid < NG * TT) sm->tb[tid] = tb[tid];
    if (tid < NG * NE) sm->gb[tid] = gb[tid];
    if (tid < NG * 2)  sm->ob[tid] = ob[tid];
    __syncthreads();

    u64 gl[12];
    #pragma unroll
    for (int j = 0; j < 12; j++) {
        if (h == 0) {
            int g = j >> 2, e2 = j & 3;
            gl[j] = pack2(sm->gb[g * NE + 2 * e2], sm->gb[g * NE + 2 * e2 + 1]);
        } else gl[j] = 0ull;
    }
    {
        const float4* xp = (const float4*)&g_x[(long)b * FEAT + h * 80];
        #pragma unroll 5
        for (int kk = 0; kk < 20; kk++) {
            float4 x4 = xp[kk];
            int kbase = h * 80 + kk * 4;
            float xs[4] = {x4.x, x4.y, x4.z, x4.w};
            #pragma unroll
            for (int c = 0; c < 4; c++) {
                u64 xv = pack2(xs[c], xs[c]);
                const ulonglong2* gwrow = (const ulonglong2*)&sm->gw[kbase + c][0];
                #pragma unroll
                for (int q = 0; q < 6; q++) {
                    ulonglong2 wp = gwrow[q];
                    gl[2 * q]     = ffma2(xv, wp.x, gl[2 * q]);
                    gl[2 * q + 1] = ffma2(xv, wp.y, gl[2 * q + 1]);
                }
            }
        }
    }

    if (h == 1) {
        #pragma unroll
        for (int j = 0; j < 12; j++) sm->red[bl][j] = gl[j];
    }
    __syncthreads();
    if (h == 0) {
        float* gout = (float*)&sm->red[bl][0];
        #pragma unroll
        for (int g = 0; g < NG; g++) {
            float lg[NE];
            #pragma unroll
            for (int e2 = 0; e2 < 4; e2++) {
                u64 v = fadd2(gl[g * 4 + e2], sm->red[bl][g * 4 + e2]);
                unpack2(v, lg[2 * e2], lg[2 * e2 + 1]);
            }
            float m = lg[0];
            #pragma unroll
            for (int e = 1; e < NE; e++) m = fmaxf(m, lg[e]);
            float sum = 0.f;
            #pragma unroll
            for (int e = 0; e < NE; e++) { lg[e] = __expf(lg[e] - m); sum += lg[e]; }
            float inv = __fdividef(1.f, sum);
            #pragma unroll
            for (int e = 0; e < NE; e++) gout[g * NE + e] = lg[e] * inv;
        }
    }
    __syncthreads();
    float gate[NG][NE];
    {
        const float* gin = (const float*)&sm->red[bl][0];
        #pragma unroll
        for (int g = 0; g < NG; g++)
            #pragma unroll
            for (int e = 0; e < NE; e++) gate[g][e] = gin[g * NE + e];
    }
    __syncthreads();

    u64 ta[48];
    #pragma unroll
    for (int j = 0; j < 48; j++) {
        if (h == 0) {
            int g = j >> 4, t2 = j & 15;
            ta[j] = pack2(sm->tb[g * TT + 2 * t2], sm->tb[g * TT + 2 * t2 + 1]);
        } else ta[j] = 0ull;
    }
    {
        const float* ebase = &g_exp[(long)b * NCOLS];
        #pragma unroll 1
        for (int sc = 0; sc < 8; sc++) {
            int s = h * 32 + sc * 4;
            float4 v[NE];
            #pragma unroll
            for (int e = 0; e < NE; e++)
                v[e] = *(const float4*)&ebase[e * SS + s];
            #pragma unroll
            for (int ss = 0; ss < 4; ss++) {
                float ve[NE];
                #pragma unroll
                for (int e = 0; e < NE; e++)
                    ve[e] = (ss == 0) ? v[e].x : (ss == 1) ? v[e].y : (ss == 2) ? v[e].z : v[e].w;
                u64 m2[NG];
                #pragma unroll
                for (int g = 0; g < NG; g++) {
                    float m = 0.f;
                    #pragma unroll
                    for (int e = 0; e < NE; e++) m = fmaf(gate[g][e], ve[e], m);
                    m2[g] = pack2(m, m);
                }
                const ulonglong2* twrow = (const ulonglong2*)&sm->tw[s + ss][0];
                #pragma unroll
                for (int q = 0; q < 24; q++) {
                    ulonglong2 wp = twrow[q];
                    int g = q >> 3;
                    ta[2 * q]     = ffma2(m2[g], wp.x, ta[2 * q]);
                    ta[2 * q + 1] = ffma2(m2[g], wp.y, ta[2 * q + 1]);
                }
            }
        }
    }

    if (h == 1) {
        #pragma unroll
        for (int j = 0; j < 48; j++) sm->red[bl][j] = ta[j];
    }
    __syncthreads();
    if (h == 0) {
        float ctr0 = 0.f, ctr1 = 0.f, cvr0 = 0.f, cvr1 = 0.f, imp1 = 0.f;
        #pragma unroll
        for (int g = 0; g < NG; g++) {
            float l0 = sm->ob[g * 2 + 0], l1 = sm->ob[g * 2 + 1];
            #pragma unroll
            for (int t2 = 0; t2 < 16; t2++) {
                u64 v = fadd2(ta[g * 16 + t2], sm->red[bl][g * 16 + t2]);
                float a, c;
                unpack2(v, a, c);
                a = fmaxf(a, 0.f); c = fmaxf(c, 0.f);
                l0 = fmaf(a, sm->ow[(g * TT + 2 * t2) * 2 + 0], l0);
                l1 = fmaf(a, sm->ow[(g * TT + 2 * t2) * 2 + 1], l1);
                l0 = fmaf(c, sm->ow[(g * TT + 2 * t2 + 1) * 2 + 0], l0);
                l1 = fmaf(c, sm->ow[(g * TT + 2 * t2 + 1) * 2 + 1], l1);
            }
            float mm = fmaxf(l0, l1);
            float e0 = __expf(l0 - mm), e1 = __expf(l1 - mm);
            float inv = __fdividef(1.f, e0 + e1);
            float p0 = fminf(fmaxf(e0 * inv, 1e-15f), 1.f - 1e-15f);
            float p1 = fminf(fmaxf(e1 * inv, 1e-15f), 1.f - 1e-15f);
            if (g == 0)      { ctr0 = p0; ctr1 = p1; }
            else if (g == 1) { cvr0 = p0; cvr1 = p1; }
            else             { imp1 = p1; }
        }
        float cc = ctr1 * cvr1;
        float* o = out + (long)b * 10;
        o[0] = ctr0; o[1] = ctr1; o[2] = ctr1;
        o[3] = cvr0; o[4] = cvr1; o[5] = cvr1;
        o[6] = 1.f - cc; o[7] = cc; o[8] = cc;
        o[9] = imp1;
    }
}

extern "C" void kernel_launch(void* const* d_in, const int* in_sizes, int n_in,
                              void* d_out, int out_size) {
    const int*   ids = (const int*)d_in[0];
    const float* emb = (const float*)d_in[1];
    const float* ew  = (const float*)d_in[2];
    const float* eb  = (const float*)d_in[3];
    const float* gw  = (const float*)d_in[4];
    const float* gb  = (const float*)d_in[5];
    const float* tw  = (const float*)d_in[6];
    const float* tb  = (const float*)d_in[7];
    const float* ow  = (const float*)d_in[8];
    const float* ob  = (const float*)d_in[9];
    float* out = (float*)d_out;

    cudaFuncSetAttribute(expert_mma_kernel, cudaFuncAttributeMaxDynamicSharedMemorySize, DYN_SMEM);
    cudaFuncSetAttribute(head_kernel, cudaFuncAttributeMaxDynamicSharedMemorySize,
                         (int)sizeof(HeadSmem));

    wprep_kernel<<<(NCOLS * FEAT + 255) / 256, 256>>>(ew);
    gather_kernel<<<(NF * BATCH) / 64, 256>>>(ids, (const float4*)emb);
    expert_mma_kernel<<<dim3(BATCH / TM, NCOLS / TN), 256, DYN_SMEM>>>(eb);
    head_kernel<<<BATCH / 64, 128, sizeof(HeadSmem)>>>(gw, gb, tw, tb, ow, ob, out);
}